// round 13
// baseline (speedup 1.0000x reference)
#include <cuda_runtime.h>

// ---------------------------------------------------------------------------
// Problem constants
// ---------------------------------------------------------------------------
#define BATCH   4
#define NPOS    196608          // 256*256*3 positions per batch
#define F       64              // filters
#define NCHUNK  512             // chunks per batch (scan granularity)
#define CS      384             // positions per chunk (multiple of 3)
#define TP      24              // positions staged in smem per tile (8 pixels)
#define FT      24              // final-kernel tile positions
#define SCALE   (1.0f/196608.0f)

typedef unsigned long long ull;

// ---------------------------------------------------------------------------
// Scratch (device globals: allocation-free per harness rules)
// ---------------------------------------------------------------------------
__device__ float g_bufA[(size_t)BATCH * NPOS * F];   // 201 MB
__device__ float g_bufB[(size_t)BATCH * NPOS * F];   // 201 MB
__device__ float g_csum[BATCH * NCHUNK * F];
__device__ float g_off [BATCH * NCHUNK * F];

// ---------------------------------------------------------------------------
// Packed f32x2 helpers (sm_103a packed FMA pipe)
// ---------------------------------------------------------------------------
__device__ __forceinline__ ull pack2(float a, float b) {
    ull r; asm("mov.b64 %0, {%1,%2};" : "=l"(r) : "f"(a), "f"(b)); return r;
}
__device__ __forceinline__ void unpack2(ull v, float& a, float& b) {
    asm("mov.b64 {%0,%1}, %2;" : "=f"(a), "=f"(b) : "l"(v));
}
__device__ __forceinline__ ull ffma2(ull a, ull b, ull c) {
    ull d; asm("fma.rn.f32x2 %0, %1, %2, %3;" : "=l"(d) : "l"(a), "l"(b), "l"(c));
    return d;
}

// ---------------------------------------------------------------------------
// Layer 0: x -> ReLU(w0[c]*x + b0[c]) -> chunk-local cumsum into g_bufA
// One block per (batch, chunk); 64 threads, thread = feature e.
// ---------------------------------------------------------------------------
__global__ __launch_bounds__(64)
void layer0_kernel(const int* __restrict__ ex,
                   const float* __restrict__ W0,   // [3][1][64]
                   const float* __restrict__ b0) { // [3][64]
    int batch = blockIdx.x / NCHUNK;
    int chunk = blockIdx.x % NCHUNK;
    int e = threadIdx.x;
    size_t base = (size_t)batch * NPOS + (size_t)chunk * CS;

    float w[3], bb[3];
#pragma unroll
    for (int c = 0; c < 3; ++c) { w[c] = W0[c * 64 + e]; bb[c] = b0[c * 64 + e]; }

    __shared__ int xs[96];
    float run = 0.0f;
    float* out = g_bufA + base * F;
    const int* exb = ex + base;

    for (int tile = 0; tile < CS / 96; ++tile) {
        __syncthreads();
        xs[threadIdx.x] = exb[tile * 96 + threadIdx.x];
        if (threadIdx.x < 32) xs[threadIdx.x + 64] = exb[tile * 96 + threadIdx.x + 64];
        __syncthreads();
#pragma unroll
        for (int px = 0; px < 32; ++px) {
#pragma unroll
            for (int c = 0; c < 3; ++c) {
                int p = px * 3 + c;
                float xf = (float)xs[p] * 0.25f - 1.0f;   // /8*2-1
                float v = fmaxf(fmaf(w[c], xf, bb[c]), 0.0f);
                run += v;
                out[(size_t)(tile * 96 + p) * F + e] = run;
            }
        }
    }
    g_csum[(batch * NCHUNK + chunk) * F + e] = run;
}

// ---------------------------------------------------------------------------
// Parallel exclusive scan over chunk sums -> per-chunk offsets.
// grid = (BATCH, F), block = 512 threads (one per chunk).
// ---------------------------------------------------------------------------
__global__ __launch_bounds__(512)
void scan_kernel() {
    int b = blockIdx.x;
    int e = blockIdx.y;
    int t = threadIdx.x;            // chunk index 0..511
    int lane = t & 31, w = t >> 5;  // 16 warps

    int i = (b * NCHUNK + t) * F + e;
    float v = g_csum[i];

    // inclusive warp scan
    float s = v;
#pragma unroll
    for (int d = 1; d < 32; d <<= 1) {
        float n = __shfl_up_sync(0xffffffffu, s, d);
        if (lane >= d) s += n;
    }

    __shared__ float ws[16];
    if (lane == 31) ws[w] = s;
    __syncthreads();
    if (t < 16) {
        float x = ws[t];
#pragma unroll
        for (int d = 1; d < 16; d <<= 1) {
            float n = __shfl_up_sync(0x0000ffffu, x, d);
            if (t >= d) x += n;
        }
        ws[t] = x;
    }
    __syncthreads();

    float warp_pre = (w > 0) ? ws[w - 1] : 0.0f;
    g_off[i] = warp_pre + (s - v);   // exclusive prefix
}

// ---------------------------------------------------------------------------
// Mid layers 1..3: u = (in + off)*SCALE ; v = ReLU(W[c]^T u + b[c]) ;
// chunk-local cumsum -> out.   128 threads: thread = (feature e, d-half h).
// Weights packed once into registers; u read from smem as ulonglong2 so the
// LDS.128's register quad feeds fma.rn.f32x2 directly (no pack MOVs).
// ---------------------------------------------------------------------------
__global__ __launch_bounds__(128, 3)
void layer_kernel(int src,
                  const float* __restrict__ W,      // [3][64][64] (c,d,e)
                  const float* __restrict__ bias) { // [3][64]
    int batch = blockIdx.x / NCHUNK;
    int chunk = blockIdx.x % NCHUNK;
    int tid = threadIdx.x;
    int lane = tid & 31, wrp = tid >> 5;
    int e = wrp * 16 + (lane >> 1);
    int h = lane & 1;

    const float* in = src ? g_bufB : g_bufA;
    float*       out = src ? g_bufA : g_bufB;
    size_t base = (size_t)batch * NPOS + (size_t)chunk * CS;
    in  += base * F;
    out += base * F;

    // Register-resident weight columns: d in {8j + 4h + 0..3}
    ull wr[3][8][2];
#pragma unroll
    for (int c = 0; c < 3; ++c)
#pragma unroll
        for (int j = 0; j < 8; ++j) {
            int d0 = 8 * j + 4 * h;
            wr[c][j][0] = pack2(W[(c * 64 + d0    ) * 64 + e], W[(c * 64 + d0 + 1) * 64 + e]);
            wr[c][j][1] = pack2(W[(c * 64 + d0 + 2) * 64 + e], W[(c * 64 + d0 + 3) * 64 + e]);
        }
    float bs[3];
#pragma unroll
    for (int c = 0; c < 3; ++c) bs[c] = bias[c * 64 + e];

    float offd = g_off[(batch * NCHUNK + chunk) * F + (tid & 63)];

    __shared__ float us[TP * F];   // 6 KB
    float run = 0.0f;

    for (int tile = 0; tile < CS / TP; ++tile) {
        __syncthreads();
        const float* inT = in + (size_t)tile * TP * F;
#pragma unroll
        for (int k = 0; k < TP * F / 128; ++k) {   // 12 coalesced loads/thread
            int idx = tid + k * 128;               // d = idx & 63 == tid & 63
            us[idx] = (inT[idx] + offd) * SCALE;
        }
        __syncthreads();

        for (int px = 0; px < TP / 3; ++px) {
#pragma unroll
            for (int c = 0; c < 3; ++c) {
                int p = px * 3 + c;
                ull accA = 0ull, accB = 0ull;
#pragma unroll
                for (int j = 0; j < 8; ++j) {
                    // 16B-aligned (byte off = 32j + 16h): one LDS.128, operand
                    // pairs consumed as packed f32x2 with zero MOVs.
                    ulonglong2 uv = *reinterpret_cast<const ulonglong2*>(
                        &us[p * F + 8 * j + 4 * h]);
                    accA = ffma2(wr[c][j][0], uv.x, accA);
                    accB = ffma2(wr[c][j][1], uv.y, accB);
                }
                float a0, a1, c0, c1;
                unpack2(accA, a0, a1);
                unpack2(accB, c0, c1);
                float part = (a0 + a1) + (c0 + c1);
                float tot = part + __shfl_xor_sync(0xffffffffu, part, 1) + bs[c];
                run += fmaxf(tot, 0.0f);
                if (h == 0) out[(size_t)(tile * TP + p) * F + e] = run;
            }
        }
    }
    if (h == 0) g_csum[(batch * NCHUNK + chunk) * F + e] = run;
}

// ---------------------------------------------------------------------------
// Final dense 64 -> 8 logits. 192 threads = 24 positions x 8 outputs.
// ---------------------------------------------------------------------------
__global__ __launch_bounds__(192)
void final_kernel(const float* __restrict__ Wf,   // [3][64][8]
                  const float* __restrict__ bf,   // [3][8]
                  float* __restrict__ outp) {
    int batch = blockIdx.x / NCHUNK;
    int chunk = blockIdx.x % NCHUNK;
    int tid = threadIdx.x;
    int ps = tid >> 3;           // 0..23 (position in tile; channel = ps % 3)
    int k  = tid & 7;            // output logit
    int c  = ps % 3;

    size_t base = (size_t)batch * NPOS + (size_t)chunk * CS;
    const float* in = g_bufB + base * F;

    float wreg[64];
#pragma unroll
    for (int e = 0; e < 64; ++e) wreg[e] = Wf[(c * 64 + e) * 8 + k];
    float bv = bf[c * 8 + k];

    float offd = g_off[(batch * NCHUNK + chunk) * F + (tid & 63)];

    __shared__ float us[FT * 68];   // pad 68 for conflict-free LDS.128

    for (int tile = 0; tile < CS / FT; ++tile) {
        __syncthreads();
        const float* inT = in + (size_t)tile * FT * F;
#pragma unroll
        for (int q = 0; q < FT * F / 192; ++q) {   // 8 loads/thread
            int idx = tid + q * 192;               // d = idx & 63 == tid & 63
            int p = idx >> 6, d = idx & 63;
            us[p * 68 + d] = (inT[idx] + offd) * SCALE;
        }
        __syncthreads();

        float acc = bv;
#pragma unroll
        for (int j = 0; j < 16; ++j) {
            float4 u4 = *reinterpret_cast<const float4*>(&us[ps * 68 + 4 * j]);
            acc = fmaf(u4.x, wreg[4 * j    ], acc);
            acc = fmaf(u4.y, wreg[4 * j + 1], acc);
            acc = fmaf(u4.z, wreg[4 * j + 2], acc);
            acc = fmaf(u4.w, wreg[4 * j + 3], acc);
        }
        outp[(base + (size_t)(tile * FT + ps)) * 8 + k] = acc;
    }
}

// ---------------------------------------------------------------------------
// Launch: L0 -> scan -> (L1 -> scan) x3 -> final.  Graph-capturable: launches
// only, no allocs/syncs.  Ping-pong: L1 A->B, L2 B->A, L3 A->B, final reads B.
// ---------------------------------------------------------------------------
extern "C" void kernel_launch(void* const* d_in, const int* in_sizes, int n_in,
                              void* d_out, int out_size) {
    const int*   ex = (const int*)  d_in[0];
    const float* W0 = (const float*)d_in[1];
    const float* b0 = (const float*)d_in[2];
    const float* Wr = (const float*)d_in[3];   // [3][3][64][64]
    const float* br = (const float*)d_in[4];   // [3][3][64]
    const float* Wf = (const float*)d_in[5];   // [3][64][8]
    const float* bf = (const float*)d_in[6];   // [3][8]
    float* outp = (float*)d_out;

    dim3 grid(BATCH * NCHUNK);
    dim3 sgrid(BATCH, F);

    layer0_kernel<<<grid, 64>>>(ex, W0, b0);
    scan_kernel<<<sgrid, 512>>>();

    layer_kernel<<<grid, 128>>>(0, Wr + 0 * 3 * 64 * 64, br + 0 * 3 * 64);
    scan_kernel<<<sgrid, 512>>>();

    layer_kernel<<<grid, 128>>>(1, Wr + 1 * 3 * 64 * 64, br + 1 * 3 * 64);
    scan_kernel<<<sgrid, 512>>>();

    layer_kernel<<<grid, 128>>>(0, Wr + 2 * 3 * 64 * 64, br + 2 * 3 * 64);
    scan_kernel<<<sgrid, 512>>>();

    final_kernel<<<grid, 192>>>(Wf, bf, outp);
}

// round 14
// speedup vs baseline: 1.0869x; 1.0869x over previous
#include <cuda_runtime.h>

// ---------------------------------------------------------------------------
// Problem constants
// ---------------------------------------------------------------------------
#define BATCH   4
#define NPOS    196608          // 256*256*3 positions per batch
#define F       64              // filters
#define NCHUNK  512             // chunks per batch (scan granularity)
#define CS      384             // positions per chunk (multiple of 3)
#define TP      24              // positions staged in smem per tile (8 pixels)
#define FT      24              // final-kernel tile positions
#define SCALE   (1.0f/196608.0f)

typedef unsigned long long ull;

// ---------------------------------------------------------------------------
// Scratch (device globals: allocation-free per harness rules)
// ---------------------------------------------------------------------------
__device__ float g_bufA[(size_t)BATCH * NPOS * F];   // 201 MB
__device__ float g_bufB[(size_t)BATCH * NPOS * F];   // 201 MB
__device__ float g_csum[BATCH * NCHUNK * F];
__device__ float g_off [BATCH * NCHUNK * F];

// ---------------------------------------------------------------------------
// Packed f32x2 helpers (sm_103a packed FMA pipe)
// ---------------------------------------------------------------------------
__device__ __forceinline__ ull pack2(float a, float b) {
    ull r; asm("mov.b64 %0, {%1,%2};" : "=l"(r) : "f"(a), "f"(b)); return r;
}
__device__ __forceinline__ void unpack2(ull v, float& a, float& b) {
    asm("mov.b64 {%0,%1}, %2;" : "=f"(a), "=f"(b) : "l"(v));
}
__device__ __forceinline__ ull ffma2(ull a, ull b, ull c) {
    ull d; asm("fma.rn.f32x2 %0, %1, %2, %3;" : "=l"(d) : "l"(a), "l"(b), "l"(c));
    return d;
}
__device__ __forceinline__ ull fadd2(ull a, ull b) {
    ull d; asm("add.rn.f32x2 %0, %1, %2;" : "=l"(d) : "l"(a), "l"(b));
    return d;
}

// ---------------------------------------------------------------------------
// Layer 0: x -> ReLU(w0[c]*x + b0[c]) -> chunk-local cumsum into g_bufA
// One block per (batch, chunk); 64 threads, thread = feature e.
// ---------------------------------------------------------------------------
__global__ __launch_bounds__(64)
void layer0_kernel(const int* __restrict__ ex,
                   const float* __restrict__ W0,   // [3][1][64]
                   const float* __restrict__ b0) { // [3][64]
    int batch = blockIdx.x / NCHUNK;
    int chunk = blockIdx.x % NCHUNK;
    int e = threadIdx.x;
    size_t base = (size_t)batch * NPOS + (size_t)chunk * CS;

    float w[3], bb[3];
#pragma unroll
    for (int c = 0; c < 3; ++c) { w[c] = W0[c * 64 + e]; bb[c] = b0[c * 64 + e]; }

    __shared__ int xs[96];
    float run = 0.0f;
    float* out = g_bufA + base * F;
    const int* exb = ex + base;

    for (int tile = 0; tile < CS / 96; ++tile) {
        __syncthreads();
        xs[threadIdx.x] = exb[tile * 96 + threadIdx.x];
        if (threadIdx.x < 32) xs[threadIdx.x + 64] = exb[tile * 96 + threadIdx.x + 64];
        __syncthreads();
#pragma unroll
        for (int px = 0; px < 32; ++px) {
#pragma unroll
            for (int c = 0; c < 3; ++c) {
                int p = px * 3 + c;
                float xf = (float)xs[p] * 0.25f - 1.0f;   // /8*2-1
                float v = fmaxf(fmaf(w[c], xf, bb[c]), 0.0f);
                run += v;
                out[(size_t)(tile * 96 + p) * F + e] = run;
            }
        }
    }
    g_csum[(batch * NCHUNK + chunk) * F + e] = run;
}

// ---------------------------------------------------------------------------
// Parallel exclusive scan over chunk sums -> per-chunk offsets.
// grid = (BATCH, F), block = 512 threads (one per chunk).
// ---------------------------------------------------------------------------
__global__ __launch_bounds__(512)
void scan_kernel() {
    int b = blockIdx.x;
    int e = blockIdx.y;
    int t = threadIdx.x;            // chunk index 0..511
    int lane = t & 31, w = t >> 5;  // 16 warps

    int i = (b * NCHUNK + t) * F + e;
    float v = g_csum[i];

    float s = v;
#pragma unroll
    for (int d = 1; d < 32; d <<= 1) {
        float n = __shfl_up_sync(0xffffffffu, s, d);
        if (lane >= d) s += n;
    }

    __shared__ float ws[16];
    if (lane == 31) ws[w] = s;
    __syncthreads();
    if (t < 16) {
        float x = ws[t];
#pragma unroll
        for (int d = 1; d < 16; d <<= 1) {
            float n = __shfl_up_sync(0x0000ffffu, x, d);
            if (t >= d) x += n;
        }
        ws[t] = x;
    }
    __syncthreads();

    float warp_pre = (w > 0) ? ws[w - 1] : 0.0f;
    g_off[i] = warp_pre + (s - v);   // exclusive prefix
}

// ---------------------------------------------------------------------------
// Mid layers 1..3.  Offset fold:  W^T((in+off)*SCALE) = (W*SCALE)^T in +
// (W^T off)*SCALE, so the per-chunk offset collapses into one scalar per
// (e,c) ("offdot") and staging becomes a raw float4 copy.  Double-buffered
// smem with register prefetch: ONE barrier per 24-position tile.
// 128 threads: thread = (feature e, d-half h).
// ---------------------------------------------------------------------------
__global__ __launch_bounds__(128, 3)
void layer_kernel(int src,
                  const float* __restrict__ W,      // [3][64][64] (c,d,e)
                  const float* __restrict__ bias) { // [3][64]
    int batch = blockIdx.x / NCHUNK;
    int chunk = blockIdx.x % NCHUNK;
    int tid = threadIdx.x;
    int lane = tid & 31, wrp = tid >> 5;
    int e = wrp * 16 + (lane >> 1);
    int h = lane & 1;

    const float* in = src ? g_bufB : g_bufA;
    float*       out = src ? g_bufA : g_bufB;
    size_t base = (size_t)batch * NPOS + (size_t)chunk * CS;
    in  += base * F;
    out += base * F;

    const float* offv = g_off + (batch * NCHUNK + chunk) * F;

    // Register-resident weight columns, pre-scaled by SCALE.
    // Simultaneously accumulate offdot = sum_d W[c][d][e]*off[d]*SCALE over
    // this thread's d-range (partner half folded by the same shfl as tot).
    ull wr[3][8][2];
    float od[3];
#pragma unroll
    for (int c = 0; c < 3; ++c) {
        float acc = 0.0f;
#pragma unroll
        for (int j = 0; j < 8; ++j) {
            int d0 = 8 * j + 4 * h;
            float w0 = W[(c * 64 + d0    ) * 64 + e];
            float w1 = W[(c * 64 + d0 + 1) * 64 + e];
            float w2 = W[(c * 64 + d0 + 2) * 64 + e];
            float w3 = W[(c * 64 + d0 + 3) * 64 + e];
            acc += w0 * offv[d0] + w1 * offv[d0 + 1]
                 + w2 * offv[d0 + 2] + w3 * offv[d0 + 3];
            wr[c][j][0] = pack2(w0 * SCALE, w1 * SCALE);
            wr[c][j][1] = pack2(w2 * SCALE, w3 * SCALE);
        }
        od[c] = acc * SCALE + bias[c * 64 + e];  // folded into bias
    }

    __shared__ float us[2][TP * F];   // double buffer, 12 KB
    float run = 0.0f;

    // Preload tile 0 into buffer 0.
    {
        const float4* in4 = reinterpret_cast<const float4*>(in);
#pragma unroll
        for (int k = 0; k < TP * F / 512; ++k)             // 3 float4 / thread
            reinterpret_cast<float4*>(us[0])[tid + k * 128] = in4[tid + k * 128];
    }
    __syncthreads();

    for (int tile = 0; tile < CS / TP; ++tile) {
        int cur = tile & 1;
        // Prefetch next tile into registers (issues before the LDS consumers).
        float4 pf[3];
        if (tile + 1 < CS / TP) {
            const float4* in4 = reinterpret_cast<const float4*>(
                in + (size_t)(tile + 1) * TP * F);
#pragma unroll
            for (int k = 0; k < 3; ++k) pf[k] = in4[tid + k * 128];
        }

        for (int px = 0; px < TP / 3; ++px) {
#pragma unroll
            for (int c = 0; c < 3; ++c) {
                int p = px * 3 + c;
                ull accA = 0ull, accB = 0ull;
#pragma unroll
                for (int j = 0; j < 8; ++j) {
                    ulonglong2 uv = *reinterpret_cast<const ulonglong2*>(
                        &us[cur][p * F + 8 * j + 4 * h]);
                    accA = ffma2(wr[c][j][0], uv.x, accA);
                    accB = ffma2(wr[c][j][1], uv.y, accB);
                }
                float a0, a1;
                unpack2(fadd2(accA, accB), a0, a1);
                float part = a0 + a1 + od[c];          // od includes bias
                float tot = part + __shfl_xor_sync(0xffffffffu, part, 1);
                run += fmaxf(tot, 0.0f);
                if (h == 0) out[(size_t)(tile * TP + p) * F + e] = run;
            }
        }

        if (tile + 1 < CS / TP) {
#pragma unroll
            for (int k = 0; k < 3; ++k)
                reinterpret_cast<float4*>(us[cur ^ 1])[tid + k * 128] = pf[k];
        }
        __syncthreads();
    }
    if (h == 0) g_csum[(batch * NCHUNK + chunk) * F + e] = run;
}

// ---------------------------------------------------------------------------
// Final dense 64 -> 8 logits, with the same offset fold (weights pre-scaled,
// offset dot folded into the bias scalar).  192 threads = 24 pos x 8 logits.
// ---------------------------------------------------------------------------
__global__ __launch_bounds__(192)
void final_kernel(const float* __restrict__ Wf,   // [3][64][8]
                  const float* __restrict__ bf,   // [3][8]
                  float* __restrict__ outp) {
    int batch = blockIdx.x / NCHUNK;
    int chunk = blockIdx.x % NCHUNK;
    int tid = threadIdx.x;
    int ps = tid >> 3;           // 0..23 (position in tile; channel = ps % 3)
    int k  = tid & 7;            // output logit
    int c  = ps % 3;

    size_t base = (size_t)batch * NPOS + (size_t)chunk * CS;
    const float* in = g_bufB + base * F;
    const float* offv = g_off + (batch * NCHUNK + chunk) * F;

    float wreg[64];
    float bv = bf[c * 8 + k];
#pragma unroll
    for (int e = 0; e < 64; ++e) {
        float w = Wf[(c * 64 + e) * 8 + k];
        bv += w * offv[e] * SCALE;       // fold offset into bias
        wreg[e] = w * SCALE;             // pre-scale weight
    }

    __shared__ float us[FT * 68];   // pad 68 for conflict-free LDS.128

    for (int tile = 0; tile < CS / FT; ++tile) {
        __syncthreads();
        const float* inT = in + (size_t)tile * FT * F;
#pragma unroll
        for (int q = 0; q < FT * F / 192; ++q) {   // 8 raw copies/thread
            int idx = tid + q * 192;
            int p = idx >> 6, d = idx & 63;
            us[p * 68 + d] = inT[idx];
        }
        __syncthreads();

        float acc = bv;
#pragma unroll
        for (int j = 0; j < 16; ++j) {
            float4 u4 = *reinterpret_cast<const float4*>(&us[ps * 68 + 4 * j]);
            acc = fmaf(u4.x, wreg[4 * j    ], acc);
            acc = fmaf(u4.y, wreg[4 * j + 1], acc);
            acc = fmaf(u4.z, wreg[4 * j + 2], acc);
            acc = fmaf(u4.w, wreg[4 * j + 3], acc);
        }
        outp[(base + (size_t)(tile * FT + ps)) * 8 + k] = acc;
    }
}

// ---------------------------------------------------------------------------
// Launch: L0 -> scan -> (L1 -> scan) x3 -> final.  Graph-capturable: launches
// only, no allocs/syncs.  Ping-pong: L1 A->B, L2 B->A, L3 A->B, final reads B.
// ---------------------------------------------------------------------------
extern "C" void kernel_launch(void* const* d_in, const int* in_sizes, int n_in,
                              void* d_out, int out_size) {
    const int*   ex = (const int*)  d_in[0];
    const float* W0 = (const float*)d_in[1];
    const float* b0 = (const float*)d_in[2];
    const float* Wr = (const float*)d_in[3];   // [3][3][64][64]
    const float* br = (const float*)d_in[4];   // [3][3][64]
    const float* Wf = (const float*)d_in[5];   // [3][64][8]
    const float* bf = (const float*)d_in[6];   // [3][8]
    float* outp = (float*)d_out;

    dim3 grid(BATCH * NCHUNK);
    dim3 sgrid(BATCH, F);

    layer0_kernel<<<grid, 64>>>(ex, W0, b0);
    scan_kernel<<<sgrid, 512>>>();

    layer_kernel<<<grid, 128>>>(0, Wr + 0 * 3 * 64 * 64, br + 0 * 3 * 64);
    scan_kernel<<<sgrid, 512>>>();

    layer_kernel<<<grid, 128>>>(1, Wr + 1 * 3 * 64 * 64, br + 1 * 3 * 64);
    scan_kernel<<<sgrid, 512>>>();

    layer_kernel<<<grid, 128>>>(0, Wr + 2 * 3 * 64 * 64, br + 2 * 3 * 64);
    scan_kernel<<<sgrid, 512>>>();

    final_kernel<<<grid, 192>>>(Wf, bf, outp);
}

// round 15
// speedup vs baseline: 1.1182x; 1.0288x over previous
#include <cuda_runtime.h>

// ---------------------------------------------------------------------------
// Problem constants
// ---------------------------------------------------------------------------
#define BATCH   4
#define NPOS    196608          // 256*256*3 positions per batch
#define F       64              // filters
#define NCHUNK  512             // chunks per batch (scan granularity)
#define CS      384             // positions per chunk (multiple of 3)
#define TP      24              // positions staged in smem per tile (8 pixels)
#define FT      24              // final-kernel tile positions
#define SCALE   (1.0f/196608.0f)

typedef unsigned long long ull;

// ---------------------------------------------------------------------------
// Scratch (device globals: allocation-free per harness rules)
// ---------------------------------------------------------------------------
__device__ float g_bufA[(size_t)BATCH * NPOS * F];   // 201 MB
__device__ float g_bufB[(size_t)BATCH * NPOS * F];   // 201 MB
__device__ float g_csum[BATCH * NCHUNK * F];
__device__ float g_off [BATCH * NCHUNK * F];

// ---------------------------------------------------------------------------
// Packed f32x2 helpers (sm_103a packed FMA pipe)
// ---------------------------------------------------------------------------
__device__ __forceinline__ ull pack2(float a, float b) {
    ull r; asm("mov.b64 %0, {%1,%2};" : "=l"(r) : "f"(a), "f"(b)); return r;
}
__device__ __forceinline__ void unpack2(ull v, float& a, float& b) {
    asm("mov.b64 {%0,%1}, %2;" : "=f"(a), "=f"(b) : "l"(v));
}
__device__ __forceinline__ ull ffma2(ull a, ull b, ull c) {
    ull d; asm("fma.rn.f32x2 %0, %1, %2, %3;" : "=l"(d) : "l"(a), "l"(b), "l"(c));
    return d;
}
__device__ __forceinline__ ull fadd2(ull a, ull b) {
    ull d; asm("add.rn.f32x2 %0, %1, %2;" : "=l"(d) : "l"(a), "l"(b));
    return d;
}

// cp.async helpers (fire-and-forget gmem->smem, no register scoreboard)
__device__ __forceinline__ void cpasync16(void* dst_smem, const void* src) {
    unsigned d = (unsigned)__cvta_generic_to_shared(dst_smem);
    asm volatile("cp.async.cg.shared.global [%0], [%1], 16;" :: "r"(d), "l"(src));
}
__device__ __forceinline__ void cpasync_commit() {
    asm volatile("cp.async.commit_group;" ::: "memory");
}
__device__ __forceinline__ void cpasync_wait0() {
    asm volatile("cp.async.wait_group 0;" ::: "memory");
}

// ---------------------------------------------------------------------------
// Layer 0: x -> ReLU(w0[c]*x + b0[c]) -> chunk-local cumsum into g_bufA
// One block per (batch, chunk); 64 threads, thread = feature e.
// ---------------------------------------------------------------------------
__global__ __launch_bounds__(64)
void layer0_kernel(const int* __restrict__ ex,
                   const float* __restrict__ W0,   // [3][1][64]
                   const float* __restrict__ b0) { // [3][64]
    int batch = blockIdx.x / NCHUNK;
    int chunk = blockIdx.x % NCHUNK;
    int e = threadIdx.x;
    size_t base = (size_t)batch * NPOS + (size_t)chunk * CS;

    float w[3], bb[3];
#pragma unroll
    for (int c = 0; c < 3; ++c) { w[c] = W0[c * 64 + e]; bb[c] = b0[c * 64 + e]; }

    __shared__ int xs[96];
    float run = 0.0f;
    float* out = g_bufA + base * F;
    const int* exb = ex + base;

    for (int tile = 0; tile < CS / 96; ++tile) {
        __syncthreads();
        xs[threadIdx.x] = exb[tile * 96 + threadIdx.x];
        if (threadIdx.x < 32) xs[threadIdx.x + 64] = exb[tile * 96 + threadIdx.x + 64];
        __syncthreads();
#pragma unroll
        for (int px = 0; px < 32; ++px) {
#pragma unroll
            for (int c = 0; c < 3; ++c) {
                int p = px * 3 + c;
                float xf = (float)xs[p] * 0.25f - 1.0f;   // /8*2-1
                float v = fmaxf(fmaf(w[c], xf, bb[c]), 0.0f);
                run += v;
                out[(size_t)(tile * 96 + p) * F + e] = run;
            }
        }
    }
    g_csum[(batch * NCHUNK + chunk) * F + e] = run;
}

// ---------------------------------------------------------------------------
// Parallel exclusive scan over chunk sums -> per-chunk offsets.
// grid = (BATCH, F), block = 512 threads (one per chunk).
// ---------------------------------------------------------------------------
__global__ __launch_bounds__(512)
void scan_kernel() {
    int b = blockIdx.x;
    int e = blockIdx.y;
    int t = threadIdx.x;            // chunk index 0..511
    int lane = t & 31, w = t >> 5;  // 16 warps

    int i = (b * NCHUNK + t) * F + e;
    float v = g_csum[i];

    float s = v;
#pragma unroll
    for (int d = 1; d < 32; d <<= 1) {
        float n = __shfl_up_sync(0xffffffffu, s, d);
        if (lane >= d) s += n;
    }

    __shared__ float ws[16];
    if (lane == 31) ws[w] = s;
    __syncthreads();
    if (t < 16) {
        float x = ws[t];
#pragma unroll
        for (int d = 1; d < 16; d <<= 1) {
            float n = __shfl_up_sync(0x0000ffffu, x, d);
            if (t >= d) x += n;
        }
        ws[t] = x;
    }
    __syncthreads();

    float warp_pre = (w > 0) ? ws[w - 1] : 0.0f;
    g_off[i] = warp_pre + (s - v);   // exclusive prefix
}

// ---------------------------------------------------------------------------
// No-op parity kernel: shifts the launch index so ncu's "-s 5 -c 1" capture
// lands on a layer_kernel launch instead of a scan (profiling evidence only).
// ---------------------------------------------------------------------------
__global__ void parity_kernel() {}

// ---------------------------------------------------------------------------
// Mid layers 1..3.  Offset fold:  W^T((in+off)*SCALE) = (W*SCALE)^T in +
// (W^T off)*SCALE.  Staging is a raw 16B copy done with cp.async into a
// double buffer: fire-and-forget, one barrier per tile, no register
// scoreboard, no front-batched LDG-to-register burst.
// 128 threads: thread = (feature e, d-half h).
// ---------------------------------------------------------------------------
__global__ __launch_bounds__(128, 3)
void layer_kernel(int src,
                  const float* __restrict__ W,      // [3][64][64] (c,d,e)
                  const float* __restrict__ bias) { // [3][64]
    int batch = blockIdx.x / NCHUNK;
    int chunk = blockIdx.x % NCHUNK;
    int tid = threadIdx.x;
    int lane = tid & 31, wrp = tid >> 5;
    int e = wrp * 16 + (lane >> 1);
    int h = lane & 1;

    const float* in = src ? g_bufB : g_bufA;
    float*       out = src ? g_bufA : g_bufB;
    size_t base = (size_t)batch * NPOS + (size_t)chunk * CS;
    in  += base * F;
    out += base * F;

    const float* offv = g_off + (batch * NCHUNK + chunk) * F;

    // Register-resident weight columns, pre-scaled by SCALE.
    // offdot = sum_d W[c][d][e]*off[d]*SCALE over this thread's d-range
    // (partner half folded by the same shfl as tot); folded into bias.
    ull wr[3][8][2];
    float od[3];
#pragma unroll
    for (int c = 0; c < 3; ++c) {
        float acc = 0.0f;
#pragma unroll
        for (int j = 0; j < 8; ++j) {
            int d0 = 8 * j + 4 * h;
            float w0 = W[(c * 64 + d0    ) * 64 + e];
            float w1 = W[(c * 64 + d0 + 1) * 64 + e];
            float w2 = W[(c * 64 + d0 + 2) * 64 + e];
            float w3 = W[(c * 64 + d0 + 3) * 64 + e];
            acc += w0 * offv[d0] + w1 * offv[d0 + 1]
                 + w2 * offv[d0 + 2] + w3 * offv[d0 + 3];
            wr[c][j][0] = pack2(w0 * SCALE, w1 * SCALE);
            wr[c][j][1] = pack2(w2 * SCALE, w3 * SCALE);
        }
        od[c] = acc * SCALE + bias[c * 64 + e];  // folded into bias
    }

    __shared__ float us[2][TP * F];   // double buffer, 12 KB
    float run = 0.0f;

    // Preload tile 0 into buffer 0 (cp.async).
    {
        const float4* in4 = reinterpret_cast<const float4*>(in);
        float4* s4 = reinterpret_cast<float4*>(us[0]);
#pragma unroll
        for (int k = 0; k < 3; ++k)
            cpasync16(&s4[tid + k * 128], &in4[tid + k * 128]);
        cpasync_commit();
        cpasync_wait0();
    }
    __syncthreads();

    for (int tile = 0; tile < CS / TP; ++tile) {
        int cur = tile & 1;
        // Fire-and-forget prefetch of next tile into the back buffer.
        if (tile + 1 < CS / TP) {
            const float4* in4 = reinterpret_cast<const float4*>(
                in + (size_t)(tile + 1) * TP * F);
            float4* s4 = reinterpret_cast<float4*>(us[cur ^ 1]);
#pragma unroll
            for (int k = 0; k < 3; ++k)
                cpasync16(&s4[tid + k * 128], &in4[tid + k * 128]);
            cpasync_commit();
        }

        for (int px = 0; px < TP / 3; ++px) {
#pragma unroll
            for (int c = 0; c < 3; ++c) {
                int p = px * 3 + c;
                ull accA = 0ull, accB = 0ull;
#pragma unroll
                for (int j = 0; j < 8; ++j) {
                    ulonglong2 uv = *reinterpret_cast<const ulonglong2*>(
                        &us[cur][p * F + 8 * j + 4 * h]);
                    accA = ffma2(wr[c][j][0], uv.x, accA);
                    accB = ffma2(wr[c][j][1], uv.y, accB);
                }
                float a0, a1;
                unpack2(fadd2(accA, accB), a0, a1);
                float part = a0 + a1 + od[c];          // od includes bias
                float tot = part + __shfl_xor_sync(0xffffffffu, part, 1);
                run += fmaxf(tot, 0.0f);
                if (h == 0) out[(size_t)(tile * TP + p) * F + e] = run;
            }
        }

        cpasync_wait0();
        __syncthreads();
    }
    if (h == 0) g_csum[(batch * NCHUNK + chunk) * F + e] = run;
}

// ---------------------------------------------------------------------------
// Final dense 64 -> 8 logits, offset folded into bias; cp.async double
// buffer, one barrier per tile.  192 threads = 24 pos x 8 logits.
// ---------------------------------------------------------------------------
__global__ __launch_bounds__(192)
void final_kernel(const float* __restrict__ Wf,   // [3][64][8]
                  const float* __restrict__ bf,   // [3][8]
                  float* __restrict__ outp) {
    int batch = blockIdx.x / NCHUNK;
    int chunk = blockIdx.x % NCHUNK;
    int tid = threadIdx.x;
    int ps = tid >> 3;           // 0..23 (position in tile; channel = ps % 3)
    int k  = tid & 7;            // output logit
    int c  = ps % 3;

    size_t base = (size_t)batch * NPOS + (size_t)chunk * CS;
    const float* in = g_bufB + base * F;
    const float* offv = g_off + (batch * NCHUNK + chunk) * F;

    float wreg[64];
    float bv = bf[c * 8 + k];
#pragma unroll
    for (int e = 0; e < 64; ++e) {
        float w = Wf[(c * 64 + e) * 8 + k];
        bv += w * offv[e] * SCALE;       // fold offset into bias
        wreg[e] = w * SCALE;             // pre-scale weight
    }

    __shared__ float us[2][FT * 68];   // pad 68; quads stay 16B aligned

    // Preload tile 0: FT*F/4 = 384 quads, threads 0..191 copy 2 each.
    {
#pragma unroll
        for (int q = 0; q < 2; ++q) {
            int idx = tid + q * 192;          // quad index
            int p = idx >> 4, qd = idx & 15;  // position, quad-within-row
            cpasync16(&us[0][p * 68 + qd * 4], in + p * 64 + qd * 4);
        }
        cpasync_commit();
        cpasync_wait0();
    }
    __syncthreads();

    for (int tile = 0; tile < CS / FT; ++tile) {
        int cur = tile & 1;
        if (tile + 1 < CS / FT) {
            const float* inT = in + (size_t)(tile + 1) * FT * F;
#pragma unroll
            for (int q = 0; q < 2; ++q) {
                int idx = tid + q * 192;
                int p = idx >> 4, qd = idx & 15;
                cpasync16(&us[cur ^ 1][p * 68 + qd * 4], inT + p * 64 + qd * 4);
            }
            cpasync_commit();
        }

        float acc = bv;
#pragma unroll
        for (int j = 0; j < 16; ++j) {
            float4 u4 = *reinterpret_cast<const float4*>(&us[cur][ps * 68 + 4 * j]);
            acc = fmaf(u4.x, wreg[4 * j    ], acc);
            acc = fmaf(u4.y, wreg[4 * j + 1], acc);
            acc = fmaf(u4.z, wreg[4 * j + 2], acc);
            acc = fmaf(u4.w, wreg[4 * j + 3], acc);
        }
        outp[(base + (size_t)(tile * FT + ps)) * 8 + k] = acc;

        cpasync_wait0();
        __syncthreads();
    }
}

// ---------------------------------------------------------------------------
// Launch: L0 -> scan -> L1 -> scan -> parity -> L2 -> scan -> L3 -> scan ->
// final.  The parity kernel makes the 6th launch (ncu -s 5 -c 1) a
// layer_kernel.  Graph-capturable: launches only, no allocs/syncs.
// Ping-pong: L1 A->B, L2 B->A, L3 A->B, final reads B.
// ---------------------------------------------------------------------------
extern "C" void kernel_launch(void* const* d_in, const int* in_sizes, int n_in,
                              void* d_out, int out_size) {
    const int*   ex = (const int*)  d_in[0];
    const float* W0 = (const float*)d_in[1];
    const float* b0 = (const float*)d_in[2];
    const float* Wr = (const float*)d_in[3];   // [3][3][64][64]
    const float* br = (const float*)d_in[4];   // [3][3][64]
    const float* Wf = (const float*)d_in[5];   // [3][64][8]
    const float* bf = (const float*)d_in[6];   // [3][8]
    float* outp = (float*)d_out;

    dim3 grid(BATCH * NCHUNK);
    dim3 sgrid(BATCH, F);

    layer0_kernel<<<grid, 64>>>(ex, W0, b0);                      // 1
    scan_kernel<<<sgrid, 512>>>();                                // 2

    layer_kernel<<<grid, 128>>>(0, Wr + 0 * 3 * 64 * 64, br + 0 * 3 * 64); // 3
    scan_kernel<<<sgrid, 512>>>();                                // 4

    parity_kernel<<<1, 32>>>();                                   // 5

    layer_kernel<<<grid, 128>>>(1, Wr + 1 * 3 * 64 * 64, br + 1 * 3 * 64); // 6 <- ncu
    scan_kernel<<<sgrid, 512>>>();                                // 7

    layer_kernel<<<grid, 128>>>(0, Wr + 2 * 3 * 64 * 64, br + 2 * 3 * 64); // 8
    scan_kernel<<<sgrid, 512>>>();                                // 9

    final_kernel<<<grid, 192>>>(Wf, bf, outp);                    // 10
}

// round 16
// speedup vs baseline: 1.1607x; 1.0380x over previous
#include <cuda_runtime.h>

// ---------------------------------------------------------------------------
// Problem constants
// ---------------------------------------------------------------------------
#define BATCH   4
#define NPOS    196608          // 256*256*3 positions per batch
#define F       64              // filters
#define NCHUNK  512             // chunks per batch (scan granularity)
#define CS      384             // positions per chunk (multiple of 3)
#define TP      48              // positions staged in smem per tile (16 pixels)
#define NT      (CS / TP)       // 8 tiles per chunk
#define FT      24              // final-kernel tile positions
#define SCALE   (1.0f/196608.0f)

typedef unsigned long long ull;

// ---------------------------------------------------------------------------
// Scratch (device globals: allocation-free per harness rules)
// ---------------------------------------------------------------------------
__device__ float g_bufA[(size_t)BATCH * NPOS * F];   // 201 MB
__device__ float g_bufB[(size_t)BATCH * NPOS * F];   // 201 MB
__device__ float g_csum[BATCH * NCHUNK * F];
__device__ float g_off [BATCH * NCHUNK * F];

// ---------------------------------------------------------------------------
// Packed f32x2 helpers (sm_103a packed FMA pipe)
// ---------------------------------------------------------------------------
__device__ __forceinline__ ull pack2(float a, float b) {
    ull r; asm("mov.b64 %0, {%1,%2};" : "=l"(r) : "f"(a), "f"(b)); return r;
}
__device__ __forceinline__ void unpack2(ull v, float& a, float& b) {
    asm("mov.b64 {%0,%1}, %2;" : "=f"(a), "=f"(b) : "l"(v));
}
__device__ __forceinline__ ull ffma2(ull a, ull b, ull c) {
    ull d; asm("fma.rn.f32x2 %0, %1, %2, %3;" : "=l"(d) : "l"(a), "l"(b), "l"(c));
    return d;
}
__device__ __forceinline__ ull fadd2(ull a, ull b) {
    ull d; asm("add.rn.f32x2 %0, %1, %2;" : "=l"(d) : "l"(a), "l"(b));
    return d;
}

// cp.async helpers (fire-and-forget gmem->smem, no register scoreboard)
__device__ __forceinline__ void cpasync16(void* dst_smem, const void* src) {
    unsigned d = (unsigned)__cvta_generic_to_shared(dst_smem);
    asm volatile("cp.async.cg.shared.global [%0], [%1], 16;" :: "r"(d), "l"(src));
}
__device__ __forceinline__ void cpasync_commit() {
    asm volatile("cp.async.commit_group;" ::: "memory");
}
__device__ __forceinline__ void cpasync_wait0() {
    asm volatile("cp.async.wait_group 0;" ::: "memory");
}
__device__ __forceinline__ void cpasync_wait1() {
    asm volatile("cp.async.wait_group 1;" ::: "memory");
}

// ---------------------------------------------------------------------------
// Layer 0: x -> ReLU(w0[c]*x + b0[c]) -> chunk-local cumsum into g_bufA
// One block per (batch, chunk); 64 threads, thread = feature e.
// ---------------------------------------------------------------------------
__global__ __launch_bounds__(64)
void layer0_kernel(const int* __restrict__ ex,
                   const float* __restrict__ W0,   // [3][1][64]
                   const float* __restrict__ b0) { // [3][64]
    int batch = blockIdx.x / NCHUNK;
    int chunk = blockIdx.x % NCHUNK;
    int e = threadIdx.x;
    size_t base = (size_t)batch * NPOS + (size_t)chunk * CS;

    float w[3], bb[3];
#pragma unroll
    for (int c = 0; c < 3; ++c) { w[c] = W0[c * 64 + e]; bb[c] = b0[c * 64 + e]; }

    __shared__ int xs[96];
    float run = 0.0f;
    float* out = g_bufA + base * F;
    const int* exb = ex + base;

    for (int tile = 0; tile < CS / 96; ++tile) {
        __syncthreads();
        xs[threadIdx.x] = exb[tile * 96 + threadIdx.x];
        if (threadIdx.x < 32) xs[threadIdx.x + 64] = exb[tile * 96 + threadIdx.x + 64];
        __syncthreads();
#pragma unroll
        for (int px = 0; px < 32; ++px) {
#pragma unroll
            for (int c = 0; c < 3; ++c) {
                int p = px * 3 + c;
                float xf = (float)xs[p] * 0.25f - 1.0f;   // /8*2-1
                float v = fmaxf(fmaf(w[c], xf, bb[c]), 0.0f);
                run += v;
                out[(size_t)(tile * 96 + p) * F + e] = run;
            }
        }
    }
    g_csum[(batch * NCHUNK + chunk) * F + e] = run;
}

// ---------------------------------------------------------------------------
// Parallel exclusive scan over chunk sums -> per-chunk offsets.
// grid = (BATCH, F), block = 512 threads (one per chunk).
// ---------------------------------------------------------------------------
__global__ __launch_bounds__(512)
void scan_kernel() {
    int b = blockIdx.x;
    int e = blockIdx.y;
    int t = threadIdx.x;            // chunk index 0..511
    int lane = t & 31, w = t >> 5;  // 16 warps

    int i = (b * NCHUNK + t) * F + e;
    float v = g_csum[i];

    float s = v;
#pragma unroll
    for (int d = 1; d < 32; d <<= 1) {
        float n = __shfl_up_sync(0xffffffffu, s, d);
        if (lane >= d) s += n;
    }

    __shared__ float ws[16];
    if (lane == 31) ws[w] = s;
    __syncthreads();
    if (t < 16) {
        float x = ws[t];
#pragma unroll
        for (int d = 1; d < 16; d <<= 1) {
            float n = __shfl_up_sync(0x0000ffffu, x, d);
            if (t >= d) x += n;
        }
        ws[t] = x;
    }
    __syncthreads();

    float warp_pre = (w > 0) ? ws[w - 1] : 0.0f;
    g_off[i] = warp_pre + (s - v);   // exclusive prefix
}

// ---------------------------------------------------------------------------
// No-op parity kernel (launch-index shift for ncu capture targeting).
// ---------------------------------------------------------------------------
__global__ void parity_kernel() {}

// ---------------------------------------------------------------------------
// Mid layers 1..3.  Offset fold:  W^T((in+off)*SCALE) = (W*SCALE)^T in +
// (W^T off)*SCALE.  Staging: raw 16B cp.async into a TRIPLE buffer with
// prefetch distance 2 and wait_group 1 — the wait at each tile boundary
// refers to a group committed a full tile earlier, so it retires instantly
// and the pipeline never drains (except the last two tiles).
// 128 threads: thread = (feature e, d-half h).  One barrier per 48 positions.
// ---------------------------------------------------------------------------
__global__ __launch_bounds__(128, 3)
void layer_kernel(int src,
                  const float* __restrict__ W,      // [3][64][64] (c,d,e)
                  const float* __restrict__ bias) { // [3][64]
    int batch = blockIdx.x / NCHUNK;
    int chunk = blockIdx.x % NCHUNK;
    int tid = threadIdx.x;
    int lane = tid & 31, wrp = tid >> 5;
    int e = wrp * 16 + (lane >> 1);
    int h = lane & 1;

    const float* in = src ? g_bufB : g_bufA;
    float*       out = src ? g_bufA : g_bufB;
    size_t base = (size_t)batch * NPOS + (size_t)chunk * CS;
    in  += base * F;
    out += base * F;

    const float* offv = g_off + (batch * NCHUNK + chunk) * F;

    // Register-resident weight columns, pre-scaled by SCALE.
    // offdot folded into bias (partner half combined by the same shfl as tot).
    ull wr[3][8][2];
    float od[3];
#pragma unroll
    for (int c = 0; c < 3; ++c) {
        float acc = 0.0f;
#pragma unroll
        for (int j = 0; j < 8; ++j) {
            int d0 = 8 * j + 4 * h;
            float w0 = W[(c * 64 + d0    ) * 64 + e];
            float w1 = W[(c * 64 + d0 + 1) * 64 + e];
            float w2 = W[(c * 64 + d0 + 2) * 64 + e];
            float w3 = W[(c * 64 + d0 + 3) * 64 + e];
            acc += w0 * offv[d0] + w1 * offv[d0 + 1]
                 + w2 * offv[d0 + 2] + w3 * offv[d0 + 3];
            wr[c][j][0] = pack2(w0 * SCALE, w1 * SCALE);
            wr[c][j][1] = pack2(w2 * SCALE, w3 * SCALE);
        }
        od[c] = acc * SCALE + bias[c * 64 + e];  // folded into bias
    }

    __shared__ float us[3][TP * F];   // triple buffer, 36 KB
    float run = 0.0f;

    // Preload tiles 0 and 1 (two committed groups), wait for tile 0 only.
#pragma unroll
    for (int pt = 0; pt < 2; ++pt) {
        const float4* in4 = reinterpret_cast<const float4*>(in + (size_t)pt * TP * F);
        float4* s4 = reinterpret_cast<float4*>(us[pt]);
#pragma unroll
        for (int k = 0; k < TP * F / 512; ++k)     // 6 float4 / thread
            cpasync16(&s4[tid + k * 128], &in4[tid + k * 128]);
        cpasync_commit();
    }
    cpasync_wait1();
    __syncthreads();

    for (int tile = 0; tile < NT; ++tile) {
        int cur = tile % 3;
        // Fire-and-forget prefetch of tile+2 into the retired buffer.
        if (tile + 2 < NT) {
            const float4* in4 = reinterpret_cast<const float4*>(
                in + (size_t)(tile + 2) * TP * F);
            float4* s4 = reinterpret_cast<float4*>(us[(tile + 2) % 3]);
#pragma unroll
            for (int k = 0; k < TP * F / 512; ++k)
                cpasync16(&s4[tid + k * 128], &in4[tid + k * 128]);
            cpasync_commit();
        }

#pragma unroll 2
        for (int px = 0; px < TP / 3; ++px) {
#pragma unroll
            for (int c = 0; c < 3; ++c) {
                int p = px * 3 + c;
                ull accA = 0ull, accB = 0ull;
#pragma unroll
                for (int j = 0; j < 8; ++j) {
                    ulonglong2 uv = *reinterpret_cast<const ulonglong2*>(
                        &us[cur][p * F + 8 * j + 4 * h]);
                    accA = ffma2(wr[c][j][0], uv.x, accA);
                    accB = ffma2(wr[c][j][1], uv.y, accB);
                }
                float a0, a1;
                unpack2(fadd2(accA, accB), a0, a1);
                float part = a0 + a1 + od[c];          // od includes bias
                float tot = part + __shfl_xor_sync(0xffffffffu, part, 1);
                run += fmaxf(tot, 0.0f);
                if (h == 0) out[(size_t)(tile * TP + p) * F + e] = run;
            }
        }

        // Group committed at tile-1 (for tile+1) is already long done:
        // wait retires instantly.  Tail tiles use wait0 for the last group.
        if (tile + 2 < NT) cpasync_wait1(); else cpasync_wait0();
        __syncthreads();
    }
    if (h == 0) g_csum[(batch * NCHUNK + chunk) * F + e] = run;
}

// ---------------------------------------------------------------------------
// Final dense 64 -> 8 logits, offset folded into bias; cp.async double
// buffer, one barrier per tile.  192 threads = 24 pos x 8 logits.
// ---------------------------------------------------------------------------
__global__ __launch_bounds__(192)
void final_kernel(const float* __restrict__ Wf,   // [3][64][8]
                  const float* __restrict__ bf,   // [3][8]
                  float* __restrict__ outp) {
    int batch = blockIdx.x / NCHUNK;
    int chunk = blockIdx.x % NCHUNK;
    int tid = threadIdx.x;
    int ps = tid >> 3;           // 0..23 (position in tile; channel = ps % 3)
    int k  = tid & 7;            // output logit
    int c  = ps % 3;

    size_t base = (size_t)batch * NPOS + (size_t)chunk * CS;
    const float* in = g_bufB + base * F;
    const float* offv = g_off + (batch * NCHUNK + chunk) * F;

    float wreg[64];
    float bv = bf[c * 8 + k];
#pragma unroll
    for (int e = 0; e < 64; ++e) {
        float w = Wf[(c * 64 + e) * 8 + k];
        bv += w * offv[e] * SCALE;       // fold offset into bias
        wreg[e] = w * SCALE;             // pre-scale weight
    }

    __shared__ float us[2][FT * 68];   // pad 68; quads stay 16B aligned

    // Preload tile 0: FT*F/4 = 384 quads, threads 0..191 copy 2 each.
    {
#pragma unroll
        for (int q = 0; q < 2; ++q) {
            int idx = tid + q * 192;          // quad index
            int p = idx >> 4, qd = idx & 15;  // position, quad-within-row
            cpasync16(&us[0][p * 68 + qd * 4], in + p * 64 + qd * 4);
        }
        cpasync_commit();
        cpasync_wait0();
    }
    __syncthreads();

    for (int tile = 0; tile < CS / FT; ++tile) {
        int cur = tile & 1;
        if (tile + 1 < CS / FT) {
            const float* inT = in + (size_t)(tile + 1) * FT * F;
#pragma unroll
            for (int q = 0; q < 2; ++q) {
                int idx = tid + q * 192;
                int p = idx >> 4, qd = idx & 15;
                cpasync16(&us[cur ^ 1][p * 68 + qd * 4], inT + p * 64 + qd * 4);
            }
            cpasync_commit();
        }

        float acc = bv;
#pragma unroll
        for (int j = 0; j < 16; ++j) {
            float4 u4 = *reinterpret_cast<const float4*>(&us[cur][ps * 68 + 4 * j]);
            acc = fmaf(u4.x, wreg[4 * j    ], acc);
            acc = fmaf(u4.y, wreg[4 * j + 1], acc);
            acc = fmaf(u4.z, wreg[4 * j + 2], acc);
            acc = fmaf(u4.w, wreg[4 * j + 3], acc);
        }
        outp[(base + (size_t)(tile * FT + ps)) * 8 + k] = acc;

        cpasync_wait0();
        __syncthreads();
    }
}

// ---------------------------------------------------------------------------
// Launch: L0 -> scan -> L1 -> scan -> parity -> L2 -> scan -> L3 -> scan ->
// final.  Graph-capturable: launches only, no allocs/syncs.
// Ping-pong: L1 A->B, L2 B->A, L3 A->B, final reads B.
// ---------------------------------------------------------------------------
extern "C" void kernel_launch(void* const* d_in, const int* in_sizes, int n_in,
                              void* d_out, int out_size) {
    const int*   ex = (const int*)  d_in[0];
    const float* W0 = (const float*)d_in[1];
    const float* b0 = (const float*)d_in[2];
    const float* Wr = (const float*)d_in[3];   // [3][3][64][64]
    const float* br = (const float*)d_in[4];   // [3][3][64]
    const float* Wf = (const float*)d_in[5];   // [3][64][8]
    const float* bf = (const float*)d_in[6];   // [3][8]
    float* outp = (float*)d_out;

    dim3 grid(BATCH * NCHUNK);
    dim3 sgrid(BATCH, F);

    layer0_kernel<<<grid, 64>>>(ex, W0, b0);                      // 1
    scan_kernel<<<sgrid, 512>>>();                                // 2

    layer_kernel<<<grid, 128>>>(0, Wr + 0 * 3 * 64 * 64, br + 0 * 3 * 64); // 3
    scan_kernel<<<sgrid, 512>>>();                                // 4

    parity_kernel<<<1, 32>>>();                                   // 5

    layer_kernel<<<grid, 128>>>(1, Wr + 1 * 3 * 64 * 64, br + 1 * 3 * 64); // 6 <- ncu
    scan_kernel<<<sgrid, 512>>>();                                // 7

    layer_kernel<<<grid, 128>>>(0, Wr + 2 * 3 * 64 * 64, br + 2 * 3 * 64); // 8
    scan_kernel<<<sgrid, 512>>>();                                // 9

    final_kernel<<<grid, 192>>>(Wf, bf, outp);                    // 10
}